// round 5
// baseline (speedup 1.0000x reference)
#include <cuda_runtime.h>
#include <cuda_fp16.h>
#include <cuda.h>
#include <cstdint>

#define NPIX    100352
#define IMGPIX  3136
#define PADW    58
#define PADIMG  3364
#define NPADPIX 107648
#define BIAS    59
#define QROWS   108032
#define CCH     256
#define KTOT    2304
#define BK      64
#define NST     36        // 2304/64
#define MTILE   192
#define NCTA    561       // ceil(107648/192)

#define STG_BYTES 57344u  // A 24576 + B 32768 per stage
#define BOFFS     24576u
#define DSMEM     172032u // 3 stages

__device__ __align__(1024) __half g_Q[(size_t)QROWS * CCH];
__device__ __align__(1024) __half g_A[(size_t)QROWS * CCH];
__device__ __align__(1024) __half g_W1[KTOT * CCH];   // [k][co]
__device__ __align__(1024) __half g_W2[KTOT * CCH];

__device__ __forceinline__ float quantf(float x) {
    float s  = floorf(x * 128.0f);
    float t1 = s * 0.0078125f;
    float r  = x - t1;
    return (r < 0.0078125f - r) ? t1 : (t1 + 0.0078125f);
}
__device__ __forceinline__ uint32_t smaddr(const void* p) {
    return (uint32_t)__cvta_generic_to_shared(p);
}
__device__ __forceinline__ uint32_t sw128(uint32_t off) {
    return off ^ ((off >> 3) & 0x70);
}
__device__ __forceinline__ void mbar_init(uint32_t a, uint32_t cnt) {
    asm volatile("mbarrier.init.shared.b64 [%0], %1;" :: "r"(a), "r"(cnt) : "memory");
}
__device__ __forceinline__ void mbar_wait(uint32_t a, uint32_t parity) {
    asm volatile("{\n\t.reg .pred P1;\n\t"
                 "WL_%=:\n\t"
                 "mbarrier.try_wait.parity.shared.b64 P1, [%0], %1;\n\t"
                 "@P1 bra.uni WD_%=;\n\t"
                 "bra.uni WL_%=;\n\t"
                 "WD_%=:\n\t}"
                 :: "r"(a), "r"(parity) : "memory");
}
__device__ __forceinline__ void mbar_arrive(uint32_t a) {
    asm volatile("mbarrier.arrive.shared.b64 _, [%0];" :: "r"(a) : "memory");
}

// ---------- prep: quantize x (NCHW f32) -> g_Q (padded NHWC fp16) ----------
__global__ void __launch_bounds__(256)
prep_x_kernel(const float* __restrict__ x, __half* __restrict__ q) {
    __shared__ __half tile[64][65];
    const int p0 = blockIdx.x * 64;
    const int c0 = blockIdx.y * 64;
    const int n   = p0 / IMGPIX;
    const int rem = p0 % IMGPIX;
    const int t = threadIdx.x;
    #pragma unroll
    for (int i = 0; i < 16; ++i) {
        int c = i * 4 + (t >> 6);
        int p = t & 63;
        float v = x[(size_t)(n * 256 + c0 + c) * IMGPIX + rem + p];
        tile[c][p] = __float2half_rn(quantf(v));
    }
    __syncthreads();
    #pragma unroll
    for (int i = 0; i < 16; ++i) {
        int p = i * 4 + (t >> 6);
        int c = t & 63;
        int pr = rem + p;
        int y  = pr / 56;
        int xx = pr - y * 56;
        size_t row = (size_t)BIAS + (size_t)n * PADIMG + (y + 1) * PADW + (xx + 1);
        q[row * 256 + c0 + c] = tile[c][p];
    }
}

// ---------- prep: sign(w) OIHW -> [k][co] fp16, k = tap*256+ci ----------
__global__ void __launch_bounds__(256)
prep_w_kernel(const float* __restrict__ w1, const float* __restrict__ w2,
              __half* __restrict__ o1, __half* __restrict__ o2) {
    int j = blockIdx.x * blockDim.x + threadIdx.x;
    const int NW = KTOT * CCH;
    if (j >= 2 * NW) return;
    const float* w = (j < NW) ? w1 : w2;
    __half* o      = (j < NW) ? o1 : o2;
    int i = (j < NW) ? j : j - NW;
    int co  = i & 255;
    int k   = i >> 8;
    int ci  = k & 255;
    int tap = k >> 8;
    float v = w[(size_t)((co << 8) + ci) * 9 + tap];
    o[i] = __float2half(v >= 0.0f ? 1.0f : -1.0f);
}

// ---------- TMA + mma.sync conv: 192 pixels x 256 co, K=2304 ----------
// MODE 0: BN1 -> clip -> quantize -> padded NHWC fp16
// MODE 1: +residual -> BN2 -> clip -> NCHW fp32
template<int MODE>
__global__ void __launch_bounds__(384, 1)
conv_hm_kernel(const __grid_constant__ CUtensorMap tmA,
               const __grid_constant__ CUtensorMap tmB,
               const float* __restrict__ gg, const float* __restrict__ bbv,
               const float* __restrict__ mmn, const float* __restrict__ vvr,
               const float* __restrict__ resid, void* __restrict__ outp)
{
    extern __shared__ __align__(1024) char dsm[];
    __shared__ __align__(8) unsigned long long s_mb[6];  // full[0..2], empty[0..2]
    __shared__ float s_sc[CCH], s_sh[CCH];
    __shared__ int s_off[MTILE];
    __shared__ unsigned char s_val[MTILE];

    const int tid  = threadIdx.x;
    const int lane = tid & 31;
    const int warp = tid >> 5;
    const int wm   = warp >> 2;   // 0..2 : 64-row pixel slab
    const int wn   = warp & 3;    // 0..3 : 64-co slab
    const uint32_t smem_base = smaddr(dsm);
    const uint32_t mb0 = smaddr(s_mb);
    const int p0 = blockIdx.x * MTILE;

    if (tid < CCH) {
        float inv = gg[tid] * __frsqrt_rn(vvr[tid] + 1e-5f);
        s_sc[tid] = inv;
        s_sh[tid] = bbv[tid] - mmn[tid] * inv;
    }
    if (tid < MTILE) {
        int pp = p0 + tid;
        int ok = 0, off = 0;
        if (pp < NPADPIX) {
            int n = pp / PADIMG, rem2 = pp - n * PADIMG;
            int yy = rem2 / PADW, xx = rem2 - yy * PADW;
            if (yy >= 1 && yy <= 56 && xx >= 1 && xx <= 56) {
                ok = 1;
                off = n * (256 * IMGPIX) + (yy - 1) * 56 + (xx - 1);
            }
        }
        s_val[tid] = (unsigned char)ok;
        s_off[tid] = off;
    }
    if (tid == 0) {
        #pragma unroll
        for (int b = 0; b < 3; ++b) mbar_init(mb0 + b * 8, 1u);       // full
        #pragma unroll
        for (int b = 0; b < 3; ++b) mbar_init(mb0 + 24 + b * 8, 384u); // empty
    }
    __syncthreads();

    auto produce = [&](int s) {
        int buf = s - (s / 3) * 3;
        int k0  = s * BK;
        int tap = s >> 2;              // BK=64: 4 stages per tap
        int ci0 = (s & 3) * 64;
        int dy  = tap / 3 - 1;
        int dx  = tap - (tap / 3) * 3 - 1;
        int py  = BIAS + p0 + dy * PADW + dx;
        uint32_t fb = mb0 + buf * 8;
        uint32_t ab = smem_base + (uint32_t)buf * STG_BYTES;
        asm volatile("mbarrier.arrive.expect_tx.shared.b64 _, [%0], %1;"
                     :: "r"(fb), "r"(STG_BYTES) : "memory");
        asm volatile("cp.async.bulk.tensor.2d.shared::cta.global.tile.mbarrier::complete_tx::bytes "
                     "[%0], [%1, {%2, %3}], [%4];"
                     :: "r"(ab), "l"(&tmA), "r"(ci0), "r"(py), "r"(fb) : "memory");
        #pragma unroll
        for (int qd = 0; qd < 4; ++qd) {
            asm volatile("cp.async.bulk.tensor.2d.shared::cta.global.tile.mbarrier::complete_tx::bytes "
                         "[%0], [%1, {%2, %3}], [%4];"
                         :: "r"(ab + BOFFS + (uint32_t)qd * 8192u), "l"(&tmB),
                            "r"(qd * 64), "r"(k0), "r"(fb) : "memory");
        }
    };

    if (tid == 0) { produce(0); produce(1); produce(2); }

    float acc[4][8][4];
    #pragma unroll
    for (int a = 0; a < 4; ++a)
        #pragma unroll
        for (int b = 0; b < 8; ++b)
            #pragma unroll
            for (int c = 0; c < 4; ++c) acc[a][b][c] = 0.0f;

    // per-lane ldmatrix address components
    const uint32_t aRowByte = (uint32_t)(wm * 64 + (lane & 15)) * 128 + (uint32_t)(lane >> 4) * 16;
    const uint32_t bRowByte = (uint32_t)(lane & 15) * 128 + (uint32_t)(lane >> 4) * 16;

    #pragma unroll 1
    for (int s = 0; s < NST; ++s) {
        const int buf = s - (s / 3) * 3;
        const uint32_t ph = (uint32_t)((s / 3) & 1);
        mbar_wait(mb0 + buf * 8, ph);

        const uint32_t Ab = smem_base + (uint32_t)buf * STG_BYTES;
        const uint32_t Bb = Ab + BOFFS + (uint32_t)wn * 8192u;

        #pragma unroll
        for (int ks = 0; ks < 4; ++ks) {
            uint32_t bf[4][4];
            #pragma unroll
            for (int ni = 0; ni < 4; ++ni) {
                uint32_t off = bRowByte + (uint32_t)ks * 2048u + (uint32_t)ni * 32u;
                uint32_t a = Bb + sw128(off);
                asm volatile("ldmatrix.sync.aligned.m8n8.x4.trans.shared.b16 {%0,%1,%2,%3}, [%4];\n"
                             : "=r"(bf[ni][0]), "=r"(bf[ni][1]), "=r"(bf[ni][2]), "=r"(bf[ni][3])
                             : "r"(a));
            }
            #pragma unroll
            for (int mi = 0; mi < 4; ++mi) {
                uint32_t off = aRowByte + (uint32_t)mi * 2048u + (uint32_t)ks * 32u;
                uint32_t a = Ab + sw128(off);
                uint32_t af0, af1, af2, af3;
                asm volatile("ldmatrix.sync.aligned.m8n8.x4.shared.b16 {%0,%1,%2,%3}, [%4];\n"
                             : "=r"(af0), "=r"(af1), "=r"(af2), "=r"(af3) : "r"(a));
                #pragma unroll
                for (int nj = 0; nj < 8; ++nj) {
                    float* d = acc[mi][nj];
                    asm volatile("mma.sync.aligned.m16n8k16.row.col.f32.f16.f16.f32 "
                                 "{%0,%1,%2,%3}, {%4,%5,%6,%7}, {%8,%9}, {%0,%1,%2,%3};\n"
                                 : "+f"(d[0]), "+f"(d[1]), "+f"(d[2]), "+f"(d[3])
                                 : "r"(af0), "r"(af1), "r"(af2), "r"(af3),
                                   "r"(bf[nj >> 1][(nj & 1) * 2]), "r"(bf[nj >> 1][(nj & 1) * 2 + 1]));
                }
            }
        }
        mbar_arrive(mb0 + 24 + buf * 8);
        if (tid == 0 && s + 3 < NST) {
            mbar_wait(mb0 + 24 + buf * 8, ph);
            produce(s + 3);
        }
    }
    __syncthreads();

    const int g4 = lane >> 2, t4 = lane & 3;

    if (MODE == 0) {
        uint32_t* stg = (uint32_t*)dsm;           // [192][132] u32 (half2)
        #pragma unroll
        for (int mi = 0; mi < 4; ++mi)
            #pragma unroll
            for (int nj = 0; nj < 8; ++nj) {
                int row = wm * 64 + mi * 16 + g4;
                int col = wn * 64 + nj * 8 + t4 * 2;
                float v0 = quantf(fminf(1.f, fmaxf(-1.f, fmaf(acc[mi][nj][0], s_sc[col],     s_sh[col]))));
                float v1 = quantf(fminf(1.f, fmaxf(-1.f, fmaf(acc[mi][nj][1], s_sc[col + 1], s_sh[col + 1]))));
                float v2 = quantf(fminf(1.f, fmaxf(-1.f, fmaf(acc[mi][nj][2], s_sc[col],     s_sh[col]))));
                float v3 = quantf(fminf(1.f, fmaxf(-1.f, fmaf(acc[mi][nj][3], s_sc[col + 1], s_sh[col + 1]))));
                __half2 h01 = __floats2half2_rn(v0, v1);
                __half2 h23 = __floats2half2_rn(v2, v3);
                stg[row * 132 + (col >> 1)]       = *(uint32_t*)&h01;
                stg[(row + 8) * 132 + (col >> 1)] = *(uint32_t*)&h23;
            }
        __syncthreads();
        uint32_t* outH = (uint32_t*)outp;
        #pragma unroll 1
        for (int j = tid; j < MTILE * 128; j += 384) {
            int row = j >> 7, c = j & 127;
            if (s_val[row])
                outH[(size_t)(BIAS + p0 + row) * 128 + c] = stg[row * 132 + c];
        }
    } else {
        float* outF = (float*)outp;
        float* stg = (float*)dsm;                 // [128][193] f32
        #pragma unroll 1
        for (int h = 0; h < 2; ++h) {
            __syncthreads();
            if ((wn >> 1) == h) {
                #pragma unroll
                for (int mi = 0; mi < 4; ++mi)
                    #pragma unroll
                    for (int nj = 0; nj < 8; ++nj) {
                        int row = wm * 64 + mi * 16 + g4;
                        int cl  = (wn & 1) * 64 + nj * 8 + t4 * 2;
                        stg[cl * 193 + row]           = acc[mi][nj][0];
                        stg[(cl + 1) * 193 + row]     = acc[mi][nj][1];
                        stg[cl * 193 + row + 8]       = acc[mi][nj][2];
                        stg[(cl + 1) * 193 + row + 8] = acc[mi][nj][3];
                    }
            }
            __syncthreads();
            #pragma unroll 1
            for (int j = tid; j < 128 * MTILE; j += 384) {
                int c = j / MTILE, pp = j - c * MTILE;
                if (s_val[pp]) {
                    int cg = h * 128 + c;
                    int addr = s_off[pp] + cg * IMGPIX;
                    float v = stg[c * 193 + pp] + resid[addr];
                    v = fmaf(v, s_sc[cg], s_sh[cg]);
                    v = fminf(1.f, fmaxf(-1.f, v));
                    outF[addr] = v;
                }
            }
        }
    }
}

// ---------------- launch ----------------
typedef CUresult (*EncFn)(CUtensorMap*, CUtensorMapDataType, cuuint32_t, void*,
                          const cuuint64_t*, const cuuint64_t*, const cuuint32_t*,
                          const cuuint32_t*, CUtensorMapInterleave, CUtensorMapSwizzle,
                          CUtensorMapL2promotion, CUtensorMapFloatOOBfill);

static void make2d(EncFn enc, CUtensorMap* m, void* ptr,
                   uint64_t d0, uint64_t d1, uint64_t rowBytes,
                   uint32_t b0, uint32_t b1) {
    cuuint64_t dims[2]    = {d0, d1};
    cuuint64_t strides[1] = {rowBytes};
    cuuint32_t box[2]     = {b0, b1};
    cuuint32_t es[2]      = {1, 1};
    enc(m, CU_TENSOR_MAP_DATA_TYPE_FLOAT16, 2, ptr, dims, strides, box, es,
        CU_TENSOR_MAP_INTERLEAVE_NONE, CU_TENSOR_MAP_SWIZZLE_128B,
        CU_TENSOR_MAP_L2_PROMOTION_L2_128B, CU_TENSOR_MAP_FLOAT_OOB_FILL_NONE);
}

extern "C" void kernel_launch(void* const* d_in, const int* in_sizes, int n_in,
                              void* d_out, int out_size) {
    (void)in_sizes; (void)n_in; (void)out_size;
    const float* x  = (const float*)d_in[0];
    const float* w1 = (const float*)d_in[1];
    const float* w2 = (const float*)d_in[2];
    const float* g1 = (const float*)d_in[3];
    const float* b1 = (const float*)d_in[4];
    const float* m1 = (const float*)d_in[5];
    const float* v1 = (const float*)d_in[6];
    const float* g2 = (const float*)d_in[7];
    const float* b2 = (const float*)d_in[8];
    const float* m2 = (const float*)d_in[9];
    const float* v2 = (const float*)d_in[10];

    __half *Q, *A, *W1, *W2;
    cudaGetSymbolAddress((void**)&Q,  g_Q);
    cudaGetSymbolAddress((void**)&A,  g_A);
    cudaGetSymbolAddress((void**)&W1, g_W1);
    cudaGetSymbolAddress((void**)&W2, g_W2);

    void* fp = nullptr;
    cudaDriverEntryPointQueryResult qr;
    cudaGetDriverEntryPoint("cuTensorMapEncodeTiled", &fp, cudaEnableDefault, &qr);
    EncFn enc = (EncFn)fp;

    CUtensorMap mQ, mA, mW1, mW2;
    make2d(enc, &mQ,  Q,  CCH, QROWS, CCH * 2, BK, MTILE);
    make2d(enc, &mA,  A,  CCH, QROWS, CCH * 2, BK, MTILE);
    make2d(enc, &mW1, W1, CCH, KTOT,  CCH * 2, 64, 64);
    make2d(enc, &mW2, W2, CCH, KTOT,  CCH * 2, 64, 64);

    cudaFuncSetAttribute(conv_hm_kernel<0>, cudaFuncAttributeMaxDynamicSharedMemorySize, DSMEM);
    cudaFuncSetAttribute(conv_hm_kernel<1>, cudaFuncAttributeMaxDynamicSharedMemorySize, DSMEM);

    prep_w_kernel<<<(2 * KTOT * CCH + 255) / 256, 256>>>(w1, w2, W1, W2);
    prep_x_kernel<<<dim3(NPIX / 64, 4), 256>>>(x, Q);
    conv_hm_kernel<0><<<NCTA, 384, DSMEM>>>(mQ, mW1, g1, b1, m1, v1, nullptr, (void*)A);
    conv_hm_kernel<1><<<NCTA, 384, DSMEM>>>(mA, mW2, g2, b2, m2, v2, x, d_out);
}

// round 6
// speedup vs baseline: 1.2592x; 1.2592x over previous
#include <cuda_runtime.h>
#include <cuda_fp16.h>
#include <cuda.h>
#include <cstdint>

#define NPIX    100352
#define IMGPIX  3136
#define PADW    58
#define PADIMG  3364
#define NPADPIX 107648
#define BIAS    59
#define QROWS   108032
#define CCH     256
#define KTOT    2304
#define BK      64
#define NST     36        // 2304/64
#define MTILE   128
#define NCTA    841       // 841*128 == 107648

#define STG_BYTES 32768u  // A 16384 + B 16384 per stage
#define BOFFS     16384u
#define DSMEM     98304u  // 3 stages

__device__ __align__(1024) __half g_Q[(size_t)QROWS * CCH];
__device__ __align__(1024) __half g_A[(size_t)QROWS * CCH];
__device__ __align__(1024) __half g_W1[KTOT * CCH];   // [k][co]
__device__ __align__(1024) __half g_W2[KTOT * CCH];

__device__ __forceinline__ float quantf(float x) {
    float s  = floorf(x * 128.0f);
    float t1 = s * 0.0078125f;
    float r  = x - t1;
    return (r < 0.0078125f - r) ? t1 : (t1 + 0.0078125f);
}
__device__ __forceinline__ uint32_t smaddr(const void* p) {
    return (uint32_t)__cvta_generic_to_shared(p);
}
__device__ __forceinline__ uint32_t sw128(uint32_t off) {
    return off ^ ((off >> 3) & 0x70);
}
__device__ __forceinline__ void mbar_init(uint32_t a, uint32_t cnt) {
    asm volatile("mbarrier.init.shared.b64 [%0], %1;" :: "r"(a), "r"(cnt) : "memory");
}
__device__ __forceinline__ void mbar_wait(uint32_t a, uint32_t parity) {
    asm volatile("{\n\t.reg .pred P1;\n\t"
                 "WL_%=:\n\t"
                 "mbarrier.try_wait.parity.shared.b64 P1, [%0], %1;\n\t"
                 "@P1 bra.uni WD_%=;\n\t"
                 "bra.uni WL_%=;\n\t"
                 "WD_%=:\n\t}"
                 :: "r"(a), "r"(parity) : "memory");
}
__device__ __forceinline__ void mbar_arrive(uint32_t a) {
    asm volatile("mbarrier.arrive.shared.b64 _, [%0];" :: "r"(a) : "memory");
}

// ---------- prep: quantize x (NCHW f32) -> g_Q (padded NHWC fp16) ----------
__global__ void __launch_bounds__(256)
prep_x_kernel(const float* __restrict__ x, __half* __restrict__ q) {
    __shared__ __half tile[64][65];
    const int p0 = blockIdx.x * 64;
    const int c0 = blockIdx.y * 64;
    const int n   = p0 / IMGPIX;
    const int rem = p0 % IMGPIX;
    const int t = threadIdx.x;
    #pragma unroll
    for (int i = 0; i < 16; ++i) {
        int c = i * 4 + (t >> 6);
        int p = t & 63;
        float v = x[(size_t)(n * 256 + c0 + c) * IMGPIX + rem + p];
        tile[c][p] = __float2half_rn(quantf(v));
    }
    __syncthreads();
    #pragma unroll
    for (int i = 0; i < 16; ++i) {
        int p = i * 4 + (t >> 6);
        int c = t & 63;
        int pr = rem + p;
        int y  = pr / 56;
        int xx = pr - y * 56;
        size_t row = (size_t)BIAS + (size_t)n * PADIMG + (y + 1) * PADW + (xx + 1);
        q[row * 256 + c0 + c] = tile[c][p];
    }
}

// ---------- prep: sign(w) OIHW -> [k][co] fp16, k = tap*256+ci ----------
__global__ void __launch_bounds__(256)
prep_w_kernel(const float* __restrict__ w1, const float* __restrict__ w2,
              __half* __restrict__ o1, __half* __restrict__ o2) {
    int j = blockIdx.x * blockDim.x + threadIdx.x;
    const int NW = KTOT * CCH;
    if (j >= 2 * NW) return;
    const float* w = (j < NW) ? w1 : w2;
    __half* o      = (j < NW) ? o1 : o2;
    int i = (j < NW) ? j : j - NW;
    int co  = i & 255;
    int k   = i >> 8;
    int ci  = k & 255;
    int tap = k >> 8;
    float v = w[(size_t)((co << 8) + ci) * 9 + tap];
    o[i] = __float2half(v >= 0.0f ? 1.0f : -1.0f);
}

// ---------- TMA + mma.sync conv: 128 pixels x 128 co, 2 CTAs/SM ----------
// MODE 0: BN1 -> clip -> quantize -> padded NHWC fp16
// MODE 1: +residual -> BN2 -> clip -> NCHW fp32
template<int MODE>
__global__ void __launch_bounds__(256, 2)
conv_hm_kernel(const __grid_constant__ CUtensorMap tmA,
               const __grid_constant__ CUtensorMap tmB,
               const float* __restrict__ gg, const float* __restrict__ bbv,
               const float* __restrict__ mmn, const float* __restrict__ vvr,
               const float* __restrict__ resid, void* __restrict__ outp)
{
    extern __shared__ __align__(1024) char dsm[];
    __shared__ __align__(8) unsigned long long s_mb[6];  // full[0..2], empty[0..2]
    __shared__ float s_sc[128], s_sh[128];
    __shared__ int s_off[MTILE];
    __shared__ unsigned char s_val[MTILE];

    const int tid  = threadIdx.x;
    const int lane = tid & 31;
    const int warp = tid >> 5;
    const int wm   = warp >> 2;   // 0..1 : 64-row pixel slab
    const int wn   = warp & 3;    // 0..3 : 32-co slab
    const uint32_t smem_base = smaddr(dsm);
    const uint32_t mb0 = smaddr(s_mb);
    const int p0  = blockIdx.x * MTILE;
    const int co0 = blockIdx.y * 128;

    if (tid < 128) {
        int c = co0 + tid;
        float inv = gg[c] * __frsqrt_rn(vvr[c] + 1e-5f);
        s_sc[tid] = inv;
        s_sh[tid] = bbv[c] - mmn[c] * inv;
    }
    if (tid < MTILE) {
        int pp = p0 + tid;
        int ok = 0, off = 0;
        int n = pp / PADIMG, rem2 = pp - n * PADIMG;
        int yy = rem2 / PADW, xx = rem2 - yy * PADW;
        if (yy >= 1 && yy <= 56 && xx >= 1 && xx <= 56) {
            ok = 1;
            off = n * (256 * IMGPIX) + (yy - 1) * 56 + (xx - 1);
        }
        s_val[tid] = (unsigned char)ok;
        s_off[tid] = off;
    }
    if (tid == 0) {
        #pragma unroll
        for (int b = 0; b < 3; ++b) mbar_init(mb0 + b * 8, 1u);        // full
        #pragma unroll
        for (int b = 0; b < 3; ++b) mbar_init(mb0 + 24 + b * 8, 8u);   // empty (1/warp)
    }
    __syncthreads();

    auto produce = [&](int s) {
        int buf = s - (s / 3) * 3;
        int k0  = s * BK;
        int tap = s >> 2;              // 4 stages per tap
        int ci0 = (s & 3) * 64;
        int dy  = tap / 3 - 1;
        int dx  = tap - (tap / 3) * 3 - 1;
        int py  = BIAS + p0 + dy * PADW + dx;
        uint32_t fb = mb0 + buf * 8;
        uint32_t ab = smem_base + (uint32_t)buf * STG_BYTES;
        asm volatile("mbarrier.arrive.expect_tx.shared.b64 _, [%0], %1;"
                     :: "r"(fb), "r"(STG_BYTES) : "memory");
        asm volatile("cp.async.bulk.tensor.2d.shared::cta.global.tile.mbarrier::complete_tx::bytes "
                     "[%0], [%1, {%2, %3}], [%4];"
                     :: "r"(ab), "l"(&tmA), "r"(ci0), "r"(py), "r"(fb) : "memory");
        #pragma unroll
        for (int qd = 0; qd < 2; ++qd) {
            asm volatile("cp.async.bulk.tensor.2d.shared::cta.global.tile.mbarrier::complete_tx::bytes "
                         "[%0], [%1, {%2, %3}], [%4];"
                         :: "r"(ab + BOFFS + (uint32_t)qd * 8192u), "l"(&tmB),
                            "r"(co0 + qd * 64), "r"(k0), "r"(fb) : "memory");
        }
    };

    if (tid == 0) { produce(0); produce(1); produce(2); }

    float acc[4][4][4];
    #pragma unroll
    for (int a = 0; a < 4; ++a)
        #pragma unroll
        for (int b = 0; b < 4; ++b)
            #pragma unroll
            for (int c = 0; c < 4; ++c) acc[a][b][c] = 0.0f;

    const uint32_t aRowByte = (uint32_t)(wm * 64 + (lane & 15)) * 128 + (uint32_t)(lane >> 4) * 16;
    const uint32_t bRowByte = (uint32_t)(lane & 15) * 128 + (uint32_t)(lane >> 4) * 16
                            + (uint32_t)(wn & 1) * 64;

    #pragma unroll 1
    for (int s = 0; s < NST; ++s) {
        const int buf = s - (s / 3) * 3;
        const uint32_t ph = (uint32_t)((s / 3) & 1);
        mbar_wait(mb0 + buf * 8, ph);

        const uint32_t Ab = smem_base + (uint32_t)buf * STG_BYTES;
        const uint32_t Bb = Ab + BOFFS + (uint32_t)(wn >> 1) * 8192u;

        #pragma unroll
        for (int ks = 0; ks < 4; ++ks) {
            uint32_t bf[2][4];
            #pragma unroll
            for (int ni = 0; ni < 2; ++ni) {
                uint32_t off = bRowByte + (uint32_t)ks * 2048u + (uint32_t)ni * 32u;
                uint32_t a = Bb + sw128(off);
                asm volatile("ldmatrix.sync.aligned.m8n8.x4.trans.shared.b16 {%0,%1,%2,%3}, [%4];\n"
                             : "=r"(bf[ni][0]), "=r"(bf[ni][1]), "=r"(bf[ni][2]), "=r"(bf[ni][3])
                             : "r"(a));
            }
            #pragma unroll
            for (int mi = 0; mi < 4; ++mi) {
                uint32_t off = aRowByte + (uint32_t)mi * 2048u + (uint32_t)ks * 32u;
                uint32_t a = Ab + sw128(off);
                uint32_t af0, af1, af2, af3;
                asm volatile("ldmatrix.sync.aligned.m8n8.x4.shared.b16 {%0,%1,%2,%3}, [%4];\n"
                             : "=r"(af0), "=r"(af1), "=r"(af2), "=r"(af3) : "r"(a));
                #pragma unroll
                for (int nj = 0; nj < 4; ++nj) {
                    float* d = acc[mi][nj];
                    asm volatile("mma.sync.aligned.m16n8k16.row.col.f32.f16.f16.f32 "
                                 "{%0,%1,%2,%3}, {%4,%5,%6,%7}, {%8,%9}, {%0,%1,%2,%3};\n"
                                 : "+f"(d[0]), "+f"(d[1]), "+f"(d[2]), "+f"(d[3])
                                 : "r"(af0), "r"(af1), "r"(af2), "r"(af3),
                                   "r"(bf[nj >> 1][(nj & 1) * 2]), "r"(bf[nj >> 1][(nj & 1) * 2 + 1]));
                }
            }
        }
        if (lane == 0) mbar_arrive(mb0 + 24 + buf * 8);
        if (tid == 0 && s + 3 < NST) {
            mbar_wait(mb0 + 24 + buf * 8, ph);
            produce(s + 3);
        }
    }
    __syncthreads();

    const int g4 = lane >> 2, t4 = lane & 3;

    if (MODE == 0) {
        uint32_t* stg = (uint32_t*)dsm;           // [128][66] u32 (half2)
        #pragma unroll
        for (int mi = 0; mi < 4; ++mi)
            #pragma unroll
            for (int nj = 0; nj < 4; ++nj) {
                int row = wm * 64 + mi * 16 + g4;
                int col = wn * 32 + nj * 8 + t4 * 2;
                float v0 = quantf(fminf(1.f, fmaxf(-1.f, fmaf(acc[mi][nj][0], s_sc[col],     s_sh[col]))));
                float v1 = quantf(fminf(1.f, fmaxf(-1.f, fmaf(acc[mi][nj][1], s_sc[col + 1], s_sh[col + 1]))));
                float v2 = quantf(fminf(1.f, fmaxf(-1.f, fmaf(acc[mi][nj][2], s_sc[col],     s_sh[col]))));
                float v3 = quantf(fminf(1.f, fmaxf(-1.f, fmaf(acc[mi][nj][3], s_sc[col + 1], s_sh[col + 1]))));
                __half2 h01 = __floats2half2_rn(v0, v1);
                __half2 h23 = __floats2half2_rn(v2, v3);
                stg[row * 66 + (col >> 1)]       = *(uint32_t*)&h01;
                stg[(row + 8) * 66 + (col >> 1)] = *(uint32_t*)&h23;
            }
        __syncthreads();
        uint32_t* outH = (uint32_t*)outp;
        #pragma unroll 1
        for (int j = tid; j < MTILE * 64; j += 256) {
            int row = j >> 6, c = j & 63;
            if (s_val[row])
                outH[(size_t)(BIAS + p0 + row) * 128 + (co0 >> 1) + c] = stg[row * 66 + c];
        }
    } else {
        float* outF = (float*)outp;
        float* stg = (float*)dsm;                 // [128 co][129 pix] f32 = 66KB
        #pragma unroll
        for (int mi = 0; mi < 4; ++mi)
            #pragma unroll
            for (int nj = 0; nj < 4; ++nj) {
                int row = wm * 64 + mi * 16 + g4;
                int cl  = wn * 32 + nj * 8 + t4 * 2;
                stg[cl * 129 + row]           = acc[mi][nj][0];
                stg[(cl + 1) * 129 + row]     = acc[mi][nj][1];
                stg[cl * 129 + row + 8]       = acc[mi][nj][2];
                stg[(cl + 1) * 129 + row + 8] = acc[mi][nj][3];
            }
        __syncthreads();
        #pragma unroll 1
        for (int j = tid; j < 128 * MTILE; j += 256) {
            int c = j >> 7, pp = j & 127;
            if (s_val[pp]) {
                int addr = s_off[pp] + (co0 + c) * IMGPIX;
                float v = stg[c * 129 + pp] + resid[addr];
                v = fmaf(v, s_sc[c], s_sh[c]);
                v = fminf(1.f, fmaxf(-1.f, v));
                outF[addr] = v;
            }
        }
    }
}

// ---------------- launch ----------------
typedef CUresult (*EncFn)(CUtensorMap*, CUtensorMapDataType, cuuint32_t, void*,
                          const cuuint64_t*, const cuuint64_t*, const cuuint32_t*,
                          const cuuint32_t*, CUtensorMapInterleave, CUtensorMapSwizzle,
                          CUtensorMapL2promotion, CUtensorMapFloatOOBfill);

static void make2d(EncFn enc, CUtensorMap* m, void* ptr,
                   uint64_t d0, uint64_t d1, uint64_t rowBytes,
                   uint32_t b0, uint32_t b1) {
    cuuint64_t dims[2]    = {d0, d1};
    cuuint64_t strides[1] = {rowBytes};
    cuuint32_t box[2]     = {b0, b1};
    cuuint32_t es[2]      = {1, 1};
    enc(m, CU_TENSOR_MAP_DATA_TYPE_FLOAT16, 2, ptr, dims, strides, box, es,
        CU_TENSOR_MAP_INTERLEAVE_NONE, CU_TENSOR_MAP_SWIZZLE_128B,
        CU_TENSOR_MAP_L2_PROMOTION_L2_128B, CU_TENSOR_MAP_FLOAT_OOB_FILL_NONE);
}

extern "C" void kernel_launch(void* const* d_in, const int* in_sizes, int n_in,
                              void* d_out, int out_size) {
    (void)in_sizes; (void)n_in; (void)out_size;
    const float* x  = (const float*)d_in[0];
    const float* w1 = (const float*)d_in[1];
    const float* w2 = (const float*)d_in[2];
    const float* g1 = (const float*)d_in[3];
    const float* b1 = (const float*)d_in[4];
    const float* m1 = (const float*)d_in[5];
    const float* v1 = (const float*)d_in[6];
    const float* g2 = (const float*)d_in[7];
    const float* b2 = (const float*)d_in[8];
    const float* m2 = (const float*)d_in[9];
    const float* v2 = (const float*)d_in[10];

    __half *Q, *A, *W1, *W2;
    cudaGetSymbolAddress((void**)&Q,  g_Q);
    cudaGetSymbolAddress((void**)&A,  g_A);
    cudaGetSymbolAddress((void**)&W1, g_W1);
    cudaGetSymbolAddress((void**)&W2, g_W2);

    void* fp = nullptr;
    cudaDriverEntryPointQueryResult qr;
    cudaGetDriverEntryPoint("cuTensorMapEncodeTiled", &fp, cudaEnableDefault, &qr);
    EncFn enc = (EncFn)fp;

    CUtensorMap mQ, mA, mW1, mW2;
    make2d(enc, &mQ,  Q,  CCH, QROWS, CCH * 2, BK, MTILE);
    make2d(enc, &mA,  A,  CCH, QROWS, CCH * 2, BK, MTILE);
    make2d(enc, &mW1, W1, CCH, KTOT,  CCH * 2, 64, 64);
    make2d(enc, &mW2, W2, CCH, KTOT,  CCH * 2, 64, 64);

    cudaFuncSetAttribute(conv_hm_kernel<0>, cudaFuncAttributeMaxDynamicSharedMemorySize, DSMEM);
    cudaFuncSetAttribute(conv_hm_kernel<1>, cudaFuncAttributeMaxDynamicSharedMemorySize, DSMEM);

    prep_w_kernel<<<(2 * KTOT * CCH + 255) / 256, 256>>>(w1, w2, W1, W2);
    prep_x_kernel<<<dim3(NPIX / 64, 4), 256>>>(x, Q);
    conv_hm_kernel<0><<<dim3(NCTA, 2), 256, DSMEM>>>(mQ, mW1, g1, b1, m1, v1, nullptr, (void*)A);
    conv_hm_kernel<1><<<dim3(NCTA, 2), 256, DSMEM>>>(mA, mW2, g2, b2, m2, v2, x, d_out);
}